// round 8
// baseline (speedup 1.0000x reference)
#include <cuda_runtime.h>

// y = s1 * FWHT( g * FWHT( s2 * x ) ) per token, D = 4096 = 2^12.
// 128 threads per token, 32 floats/thread (reg bits = 5). Only 4 shuffle
// stages per token (bits i5,i6 twice); 20 butterfly stages in registers;
// 2 cross-warp smem exchanges with one symmetric XOR map.
//   L0: regs i7-11, lanes i0-4, warps(in-group) i5-6
//   L1: regs i0-4,  lanes (i5,i6,i7,i8,i9)=l2, warps i10-11
// map: addr(i) = (i0_4 ^ i5_9) | (i0_4<<5) | (i10_11<<10)  (injective)
//   L0-side accesses: bank = l ^ const   (lanes vary i0_4)  -> conflict-free
//   L1-side accesses: bank = r' ^ l2     (lanes vary i5_9)  -> conflict-free
// CTA = 256 threads = 2 token-groups; shared g_tilde buffer (same map).

#define DDIM 4096
#define ITER 4   // token-pairs per CTA -> 8 tokens/CTA

__device__ __forceinline__ float softplus_f(float x) {
    return fmaxf(x, 0.0f) + log1pf(expf(-fabsf(x)));
}

// FWHT over the 5 reg bits of v[32].
__device__ __forceinline__ void bfly5(float v[32]) {
#pragma unroll
    for (int b = 1; b < 32; b <<= 1) {
#pragma unroll
        for (int r = 0; r < 32; r++) {
            if (!(r & b)) {
                float a = v[r], c = v[r | b];
                v[r]     = a + c;
                v[r | b] = a - c;
            }
        }
    }
}

__global__ void __launch_bounds__(256, 4)
whvi_kernel(const float* __restrict__ x,
            const float* __restrict__ s1,
            const float* __restrict__ s2,
            const float* __restrict__ g_mu,
            const float* __restrict__ g_rho,
            const float* __restrict__ eps,
            float* __restrict__ out,
            int n_tokens)
{
    __shared__ float sh[2][DDIM];   // per-group exchange buffers (32 KB)
    __shared__ float gbuf[DDIM];    // g_tilde at map addresses (16 KB)

    const int t   = threadIdx.x;    // 0..255
    const int grp = t >> 7;         // token group (0/1)
    const int tid = t & 127;        // thread within group
    const int l   = tid & 31;       // hw lane; L0: = i0_4, L1: = i5_9
    const int w   = tid >> 5;       // warp in group; L0: = i5_6, L1: = i10_11

    // Base addresses for the shared-memory map.
    const int BASE0 = (l ^ w) | (l << 5);      // L0-side accesses
    const int BASE1 = l | (w << 10);           // L1-side accesses
    // L0-side per-reg offset: OFF0(r) = ((r&7)<<2) | ((r>>3)<<10)
    // L1-side per-reg offset: 33*r'  = r' | (r'<<5)

    // ---- g_tilde once per CTA (group 0 writes, map addresses) ----
    if (grp == 0) {
#pragma unroll
        for (int r = 0; r < 32; r++) {
            const int i = tid + (r << 7);
            const int a = BASE0 ^ (((r & 7) << 2) | ((r >> 3) << 10));
            gbuf[a] = g_mu[i] + softplus_f(g_rho[i]) * eps[i];
        }
    }

    float* __restrict__ shg = sh[grp];
    const float sg5 = (l & 1) ? -1.0f : 1.0f;   // sign for i5 shuffle stage
    const float sg6 = (l & 2) ? -1.0f : 1.0f;   // sign for i6 shuffle stage

    const int tokbase = blockIdx.x * (2 * ITER) + grp;

    for (int it = 0; it < ITER; it++) {
        const int tok = tokbase + 2 * it;
        if (tok >= n_tokens) break;

        float v[32];
        // ---- load x * s2 (lane-coalesced; element i = tid + r*128) ----
        const float* __restrict__ xr = x + (size_t)tok * DDIM;
#pragma unroll
        for (int r = 0; r < 32; r++) {
            const int i = tid + (r << 7);
            v[r] = xr[i] * s2[i];
        }

        bfly5(v);                                   // FWHT1 bits i7-11

        // ---- X1: L0 -> L1 ----
        __syncthreads();                            // WAR vs prev token X2 reads
#pragma unroll
        for (int r = 0; r < 32; r++)
            shg[BASE0 ^ (((r & 7) << 2) | ((r >> 3) << 10))] = v[r];
        __syncthreads();
#pragma unroll
        for (int r = 0; r < 32; r++)
            v[r] = shg[BASE1 ^ (33 * r)];

        bfly5(v);                                   // FWHT1 bits i0-4

        // ---- FWHT1 bits i5, i6 (lane shuffles) ----
#pragma unroll
        for (int r = 0; r < 32; r++) {
            float p = __shfl_xor_sync(0xffffffffu, v[r], 1);
            v[r] = fmaf(sg5, v[r], p);
        }
#pragma unroll
        for (int r = 0; r < 32; r++) {
            float p = __shfl_xor_sync(0xffffffffu, v[r], 2);
            v[r] = fmaf(sg6, v[r], p);
        }

        // ---- * g_tilde (same map, conflict-free) ----
#pragma unroll
        for (int r = 0; r < 32; r++)
            v[r] *= gbuf[BASE1 ^ (33 * r)];

        // ---- FWHT2 bits i5, i6 ----
#pragma unroll
        for (int r = 0; r < 32; r++) {
            float p = __shfl_xor_sync(0xffffffffu, v[r], 1);
            v[r] = fmaf(sg5, v[r], p);
        }
#pragma unroll
        for (int r = 0; r < 32; r++) {
            float p = __shfl_xor_sync(0xffffffffu, v[r], 2);
            v[r] = fmaf(sg6, v[r], p);
        }

        bfly5(v);                                   // FWHT2 bits i0-4

        // ---- X2: L1 -> L0 ----
        __syncthreads();                            // everyone done X1/g reads
#pragma unroll
        for (int r = 0; r < 32; r++)
            shg[BASE1 ^ (33 * r)] = v[r];
        __syncthreads();
#pragma unroll
        for (int r = 0; r < 32; r++)
            v[r] = shg[BASE0 ^ (((r & 7) << 2) | ((r >> 3) << 10))];

        bfly5(v);                                   // FWHT2 bits i7-11

        // ---- * s1, store (lane-coalesced) ----
        float* __restrict__ orow = out + (size_t)tok * DDIM;
#pragma unroll
        for (int r = 0; r < 32; r++) {
            const int i = tid + (r << 7);
            orow[i] = v[r] * s1[i];
        }
    }
}

extern "C" void kernel_launch(void* const* d_in, const int* in_sizes, int n_in,
                              void* d_out, int out_size)
{
    const float* x     = (const float*)d_in[0];
    const float* s1    = (const float*)d_in[1];
    const float* s2    = (const float*)d_in[2];
    const float* g_mu  = (const float*)d_in[3];
    const float* g_rho = (const float*)d_in[4];
    const float* eps   = (const float*)d_in[5];
    // d_in[6] = H, unused

    float* out = (float*)d_out;
    const int n_tokens = in_sizes[0] / DDIM;
    const int per_cta = 2 * ITER;
    const int grid = (n_tokens + per_cta - 1) / per_cta;

    whvi_kernel<<<grid, 256>>>(x, s1, s2, g_mu, g_rho, eps, out, n_tokens);
}

// round 9
// speedup vs baseline: 1.1685x; 1.1685x over previous
#include <cuda_runtime.h>

// y = s1 * FWHT( g * FWHT( s2 * x ) ) per token, D = 4096 = 2^12.
// 128 threads per token, 32 floats/thread (reg bits = 5). Only 4 shuffle
// stages per token (bits i5,i6 twice); 20 butterfly stages in registers;
// 2 cross-warp smem exchanges with one symmetric XOR map.
//   L0: regs i7-11, lanes i0-4, warps(in-group) i5-6
//   L1: regs i0-4,  lanes (i5,i6,i7,i8,i9)=l2, warps i10-11
// map: addr(i) = (i0_4 ^ i5_9) | (i0_4<<5) | (i10_11<<10)  (injective)
//   L0-side accesses: bank = l ^ const   (lanes vary i0_4)  -> conflict-free
//   L1-side accesses: bank = r' ^ l2     (lanes vary i5_9)  -> conflict-free
// CTA = 256 threads = 2 token-groups; shared g_tilde buffer (same map).
// R8 change vs R7: __launch_bounds__(256,3) -> 85-reg budget. R7's 64-reg cap
// forced spills (regs==64 exactly, L2 38%); algorithm unchanged.

#define DDIM 4096
#define ITER 4   // tokens per group -> 8 tokens/CTA

__device__ __forceinline__ float softplus_f(float x) {
    return fmaxf(x, 0.0f) + log1pf(expf(-fabsf(x)));
}

// FWHT over the 5 reg bits of v[32].
__device__ __forceinline__ void bfly5(float v[32]) {
#pragma unroll
    for (int b = 1; b < 32; b <<= 1) {
#pragma unroll
        for (int r = 0; r < 32; r++) {
            if (!(r & b)) {
                float a = v[r], c = v[r | b];
                v[r]     = a + c;
                v[r | b] = a - c;
            }
        }
    }
}

__global__ void __launch_bounds__(256, 3)
whvi_kernel(const float* __restrict__ x,
            const float* __restrict__ s1,
            const float* __restrict__ s2,
            const float* __restrict__ g_mu,
            const float* __restrict__ g_rho,
            const float* __restrict__ eps,
            float* __restrict__ out,
            int n_tokens)
{
    __shared__ float sh[2][DDIM];   // per-group exchange buffers (32 KB)
    __shared__ float gbuf[DDIM];    // g_tilde at map addresses (16 KB)

    const int t   = threadIdx.x;    // 0..255
    const int grp = t >> 7;         // token group (0/1)
    const int tid = t & 127;        // thread within group
    const int l   = tid & 31;       // hw lane; L0: = i0_4, L1: = i5_9
    const int w   = tid >> 5;       // warp in group; L0: = i5_6, L1: = i10_11

    // Base addresses for the shared-memory map.
    const int BASE0 = (l ^ w) | (l << 5);      // L0-side accesses
    const int BASE1 = l | (w << 10);           // L1-side accesses
    // L0-side per-reg offset: OFF0(r) = ((r&7)<<2) | ((r>>3)<<10)
    // L1-side per-reg offset: 33*r   = r | (r<<5)

    // ---- g_tilde once per CTA (group 0 writes, map addresses) ----
    if (grp == 0) {
#pragma unroll
        for (int r = 0; r < 32; r++) {
            const int i = tid + (r << 7);
            const int a = BASE0 ^ (((r & 7) << 2) | ((r >> 3) << 10));
            gbuf[a] = g_mu[i] + softplus_f(g_rho[i]) * eps[i];
        }
    }

    float* __restrict__ shg = sh[grp];
    const float sg5 = (l & 1) ? -1.0f : 1.0f;   // sign for i5 shuffle stage
    const float sg6 = (l & 2) ? -1.0f : 1.0f;   // sign for i6 shuffle stage

    const int tokbase = blockIdx.x * (2 * ITER) + grp;

    for (int it = 0; it < ITER; it++) {
        const int tok = tokbase + 2 * it;
        if (tok >= n_tokens) break;

        float v[32];
        // ---- load x * s2 (lane-coalesced; element i = tid + r*128) ----
        const float* __restrict__ xr = x + (size_t)tok * DDIM;
#pragma unroll
        for (int r = 0; r < 32; r++) {
            const int i = tid + (r << 7);
            v[r] = xr[i] * s2[i];
        }

        bfly5(v);                                   // FWHT1 bits i7-11

        // ---- X1: L0 -> L1 ----
        __syncthreads();                            // WAR vs prev token X2 reads
#pragma unroll
        for (int r = 0; r < 32; r++)
            shg[BASE0 ^ (((r & 7) << 2) | ((r >> 3) << 10))] = v[r];
        __syncthreads();
#pragma unroll
        for (int r = 0; r < 32; r++)
            v[r] = shg[BASE1 ^ (33 * r)];

        bfly5(v);                                   // FWHT1 bits i0-4

        // ---- FWHT1 bits i5, i6 (lane shuffles) ----
#pragma unroll
        for (int r = 0; r < 32; r++) {
            float p = __shfl_xor_sync(0xffffffffu, v[r], 1);
            v[r] = fmaf(sg5, v[r], p);
        }
#pragma unroll
        for (int r = 0; r < 32; r++) {
            float p = __shfl_xor_sync(0xffffffffu, v[r], 2);
            v[r] = fmaf(sg6, v[r], p);
        }

        // ---- * g_tilde (same map, conflict-free) ----
#pragma unroll
        for (int r = 0; r < 32; r++)
            v[r] *= gbuf[BASE1 ^ (33 * r)];

        // ---- FWHT2 bits i5, i6 ----
#pragma unroll
        for (int r = 0; r < 32; r++) {
            float p = __shfl_xor_sync(0xffffffffu, v[r], 1);
            v[r] = fmaf(sg5, v[r], p);
        }
#pragma unroll
        for (int r = 0; r < 32; r++) {
            float p = __shfl_xor_sync(0xffffffffu, v[r], 2);
            v[r] = fmaf(sg6, v[r], p);
        }

        bfly5(v);                                   // FWHT2 bits i0-4

        // ---- X2: L1 -> L0 ----
        __syncthreads();                            // everyone done X1/g reads
#pragma unroll
        for (int r = 0; r < 32; r++)
            shg[BASE1 ^ (33 * r)] = v[r];
        __syncthreads();
#pragma unroll
        for (int r = 0; r < 32; r++)
            v[r] = shg[BASE0 ^ (((r & 7) << 2) | ((r >> 3) << 10))];

        bfly5(v);                                   // FWHT2 bits i7-11

        // ---- * s1, store (lane-coalesced) ----
        float* __restrict__ orow = out + (size_t)tok * DDIM;
#pragma unroll
        for (int r = 0; r < 32; r++) {
            const int i = tid + (r << 7);
            orow[i] = v[r] * s1[i];
        }
    }
}

extern "C" void kernel_launch(void* const* d_in, const int* in_sizes, int n_in,
                              void* d_out, int out_size)
{
    const float* x     = (const float*)d_in[0];
    const float* s1    = (const float*)d_in[1];
    const float* s2    = (const float*)d_in[2];
    const float* g_mu  = (const float*)d_in[3];
    const float* g_rho = (const float*)d_in[4];
    const float* eps   = (const float*)d_in[5];
    // d_in[6] = H, unused

    float* out = (float*)d_out;
    const int n_tokens = in_sizes[0] / DDIM;
    const int per_cta = 2 * ITER;
    const int grid = (n_tokens + per_cta - 1) / per_cta;

    whvi_kernel<<<grid, 256>>>(x, s1, s2, g_mu, g_rho, eps, out, n_tokens);
}

// round 10
// speedup vs baseline: 1.3760x; 1.1776x over previous
#include <cuda_runtime.h>

// y = s1 * FWHT( g * FWHT( s2 * x ) ) per token, D = 4096.
// R0 dataflow (proven, 90.6us) but processing TWO tokens per register pair
// using Blackwell packed f32x2 math (FADD2/FFMA2/FMUL2). Both tokens share
// every sign, address, and transform -> all butterflies, sign-FMAs and
// elementwise scales are packed; exchanges are STS.64/LDS.64.

#define DDIM 4096
#define PAIRS 4           // token-pairs per CTA -> 8 tokens/CTA
#define NEG1 0xBF800000BF800000ULL

typedef unsigned long long u64;

__device__ __forceinline__ u64 pk2(float lo, float hi) {
    u64 u; asm("mov.b64 %0,{%1,%2};" : "=l"(u) : "f"(lo), "f"(hi)); return u;
}
__device__ __forceinline__ void up2(u64 u, float& a, float& b) {
    asm("mov.b64 {%0,%1},%2;" : "=f"(a), "=f"(b) : "l"(u));
}
__device__ __forceinline__ u64 add2(u64 a, u64 b) {
    u64 r; asm("add.rn.f32x2 %0,%1,%2;" : "=l"(r) : "l"(a), "l"(b)); return r;
}
__device__ __forceinline__ u64 mul2(u64 a, u64 b) {
    u64 r; asm("mul.rn.f32x2 %0,%1,%2;" : "=l"(r) : "l"(a), "l"(b)); return r;
}
__device__ __forceinline__ u64 fma2(u64 a, u64 b, u64 c) {
    u64 r; asm("fma.rn.f32x2 %0,%1,%2,%3;" : "=l"(r) : "l"(a), "l"(b), "l"(c)); return r;
}
// packed butterfly: (a,c) -> (a+c, a-c) for both tokens
__device__ __forceinline__ void bstep(u64& a, u64& c) {
    u64 s = add2(a, c);
    u64 d = fma2(c, NEG1, a);
    a = s; c = d;
}

__device__ __forceinline__ float softplus_f(float x) {
    return fmaxf(x, 0.0f) + log1pf(expf(-fabsf(x)));
}

__global__ void __launch_bounds__(256, 3)
whvi_kernel(const float* __restrict__ x,
            const float* __restrict__ s1,
            const float* __restrict__ s2,
            const float* __restrict__ g_mu,
            const float* __restrict__ g_rho,
            const float* __restrict__ eps,
            float* __restrict__ out,
            int n_tokens)
{
    __shared__ u64   sh2[DDIM];    // 32 KB packed exchange buffer
    __shared__ float gbuf[DDIM];   // 16 KB g_tilde (linear)

    const int t = threadIdx.x;     // 0..255
    const int l = t & 31;          // lane = element bits 0..4
    const int w = t >> 5;          // warp = element bits 9..11 (L1 layout)

    // ---- g_tilde once per CTA ----
#pragma unroll
    for (int r = 0; r < 16; r++) {
        const int i = t + (r << 8);
        gbuf[i] = g_mu[i] + softplus_f(g_rho[i]) * eps[i];
    }
    // ordered before first read by token-0's exchange-1 barrier

    const int tokA0 = blockIdx.x * (2 * PAIRS);

    for (int ip = 0; ip < PAIRS; ip++) {
        const int tokA = tokA0 + 2 * ip;
        if (tokA >= n_tokens) break;
        const int  tokB = tokA + 1;
        const bool hasB = (tokB < n_tokens);

        const float* __restrict__ xA = x + (size_t)tokA * DDIM;
        const float* __restrict__ xB = hasB ? x + (size_t)tokB * DDIM : xA;

        // ---- load both tokens, * s2, pack ----  (L0: elem i = t + 256r)
        u64 U[16];
#pragma unroll
        for (int r = 0; r < 16; r++) {
            const int i = t + (r << 8);
            const float s = s2[i];
            U[r] = pk2(xA[i] * s, xB[i] * s);
        }

        // ---- FWHT1 register stages: bits 8..11 ----
#pragma unroll
        for (int b = 1; b < 16; b <<= 1)
#pragma unroll
            for (int r = 0; r < 16; r++)
                if (!(r & b)) bstep(U[r], U[r | b]);

        // ---- FWHT1 shuffle stages: bits 0..4 ----
#pragma unroll
        for (int s = 0; s < 5; s++) {
            const int m = 1 << s;
            const float sg = (l & m) ? -1.0f : 1.0f;
            const u64 sg2 = pk2(sg, sg);
#pragma unroll
            for (int r = 0; r < 16; r++) {
                float a, b; up2(U[r], a, b);
                const float pa = __shfl_xor_sync(0xffffffffu, a, m);
                const float pb = __shfl_xor_sync(0xffffffffu, b, m);
                U[r] = fma2(U[r], sg2, pk2(pa, pb));
            }
        }

        // ---- exchange 1: L0 -> L1 (STS.64 / LDS.64) ----
        __syncthreads();
#pragma unroll
        for (int r = 0; r < 16; r++) sh2[t + (r << 8)] = U[r];
        __syncthreads();
#pragma unroll
        for (int p = 0; p < 2; p++)
#pragma unroll
            for (int k = 0; k < 8; k++)
                U[(p << 3) | k] = sh2[l + (k << 5) + (((w << 1) + p) << 8)];

        // ---- FWHT1 bits 5..7 ----
#pragma unroll
        for (int b = 1; b < 8; b <<= 1)
#pragma unroll
            for (int p = 0; p < 2; p++)
#pragma unroll
                for (int k = 0; k < 8; k++)
                    if (!(k & b)) bstep(U[(p << 3) | k], U[(p << 3) | k | b]);

        // ---- * g_tilde ----
#pragma unroll
        for (int p = 0; p < 2; p++)
#pragma unroll
            for (int k = 0; k < 8; k++) {
                const float g = gbuf[l + (k << 5) + (((w << 1) + p) << 8)];
                U[(p << 3) | k] = mul2(U[(p << 3) | k], pk2(g, g));
            }

        // ---- FWHT2 bits 5..7 ----
#pragma unroll
        for (int b = 1; b < 8; b <<= 1)
#pragma unroll
            for (int p = 0; p < 2; p++)
#pragma unroll
                for (int k = 0; k < 8; k++)
                    if (!(k & b)) bstep(U[(p << 3) | k], U[(p << 3) | k | b]);

        // ---- FWHT2 bit 8 (p) ----
#pragma unroll
        for (int k = 0; k < 8; k++) bstep(U[k], U[8 | k]);

        // ---- FWHT2 shuffle stages: bits 0..4 ----
#pragma unroll
        for (int s = 0; s < 5; s++) {
            const int m = 1 << s;
            const float sg = (l & m) ? -1.0f : 1.0f;
            const u64 sg2 = pk2(sg, sg);
#pragma unroll
            for (int r = 0; r < 16; r++) {
                float a, b; up2(U[r], a, b);
                const float pa = __shfl_xor_sync(0xffffffffu, a, m);
                const float pb = __shfl_xor_sync(0xffffffffu, b, m);
                U[r] = fma2(U[r], sg2, pk2(pa, pb));
            }
        }

        // ---- exchange 2: L1 -> L2 ----
        __syncthreads();
#pragma unroll
        for (int p = 0; p < 2; p++)
#pragma unroll
            for (int k = 0; k < 8; k++)
                sh2[l + (k << 5) + (((w << 1) + p) << 8)] = U[(p << 3) | k];
        __syncthreads();
#pragma unroll
        for (int p = 0; p < 2; p++)
#pragma unroll
            for (int j = 0; j < 8; j++)
                U[(j << 1) | p] = sh2[t + (p << 8) + (j << 9)];

        // ---- FWHT2 register stages: bits 9..11 (j) ----
#pragma unroll
        for (int b = 1; b < 8; b <<= 1)
#pragma unroll
            for (int p = 0; p < 2; p++)
#pragma unroll
                for (int j = 0; j < 8; j++)
                    if (!(j & b)) bstep(U[(j << 1) | p], U[((j | b) << 1) | p]);

        // ---- * s1, unpack, store both tokens (coalesced) ----
        float* __restrict__ oA = out + (size_t)tokA * DDIM;
        float* __restrict__ oB = out + (size_t)tokB * DDIM;
#pragma unroll
        for (int p = 0; p < 2; p++)
#pragma unroll
            for (int j = 0; j < 8; j++) {
                const int i = t + (p << 8) + (j << 9);
                const float s = s1[i];
                float a, b; up2(U[(j << 1) | p], a, b);
                oA[i] = a * s;
                if (hasB) oB[i] = b * s;
            }
    }
}

extern "C" void kernel_launch(void* const* d_in, const int* in_sizes, int n_in,
                              void* d_out, int out_size)
{
    const float* x     = (const float*)d_in[0];
    const float* s1    = (const float*)d_in[1];
    const float* s2    = (const float*)d_in[2];
    const float* g_mu  = (const float*)d_in[3];
    const float* g_rho = (const float*)d_in[4];
    const float* eps   = (const float*)d_in[5];
    // d_in[6] = H, unused

    float* out = (float*)d_out;
    const int n_tokens = in_sizes[0] / DDIM;
    const int per_cta = 2 * PAIRS;
    const int grid = (n_tokens + per_cta - 1) / per_cta;

    whvi_kernel<<<grid, 256>>>(x, s1, s2, g_mu, g_rho, eps, out, n_tokens);
}